// round 8
// baseline (speedup 1.0000x reference)
#include <cuda_runtime.h>
#include <cuda_bf16.h>
#include <math.h>
#include <stdint.h>

// Problem constants (fixed by the dataset)
#define NMAX 200000
#define EMAX 4000000
#define RREL 4
#define DDIM 64
#define NR   (NMAX * RREL)     // 800000
#define GG   64
#define CC   10

// ---------------- scratch (static __device__, no allocation) ----------------
__device__ int      g_cnt[NR];
__device__ int      g_offs[NR + 1];
__device__ int      g_cursor[NR];
__device__ int      g_csr[EMAX];
__device__ int      g_partial[256];
__device__ uint32_t g_hA[(size_t)NMAX * 32];          // bf16x2 packed, 64 dims/node
__device__ uint32_t g_hB[(size_t)NMAX * 32];
__device__ uint32_t g_Zp[(size_t)NMAX * 128];         // bf16x2 packed, 256 cols/node
__device__ uint32_t g_Wpk[3][160 * 64];               // packed bf16x2 weights: [k2][n]
__device__ float    g_pooled[GG * DDIM];

// ---------------- CSR build ----------------
__global__ void k_zero_cnt() {
    int i = blockIdx.x * blockDim.x + threadIdx.x;
    if (i < NR) g_cnt[i] = 0;
}

__global__ void k_count_edges(const int* __restrict__ tgt,
                              const int* __restrict__ et, int E) {
    int e = blockIdx.x * blockDim.x + threadIdx.x;
    if (e < E) atomicAdd(&g_cnt[tgt[e] * RREL + et[e]], 1);
}

#define SCAN_T 1024
#define SCAN_E 4096     // 4 per thread
__global__ void k_scan1() {
    __shared__ int sdata[SCAN_T];
    int b = blockIdx.x, t = threadIdx.x;
    int base = b * SCAN_E + t * 4;
    int v0 = (base + 0 < NR) ? g_cnt[base + 0] : 0;
    int v1 = (base + 1 < NR) ? g_cnt[base + 1] : 0;
    int v2 = (base + 2 < NR) ? g_cnt[base + 2] : 0;
    int v3 = (base + 3 < NR) ? g_cnt[base + 3] : 0;
    int tot = v0 + v1 + v2 + v3;
    sdata[t] = tot;
    __syncthreads();
    for (int off = 1; off < SCAN_T; off <<= 1) {
        int x = (t >= off) ? sdata[t - off] : 0;
        __syncthreads();
        sdata[t] += x;
        __syncthreads();
    }
    int excl = sdata[t] - tot;
    if (base + 0 < NR) g_offs[base + 0] = excl;
    if (base + 1 < NR) g_offs[base + 1] = excl + v0;
    if (base + 2 < NR) g_offs[base + 2] = excl + v0 + v1;
    if (base + 3 < NR) g_offs[base + 3] = excl + v0 + v1 + v2;
    if (t == SCAN_T - 1) g_partial[b] = sdata[SCAN_T - 1];
}

__global__ void k_scan2(int NB) {
    __shared__ int sdata[256];
    int t = threadIdx.x;
    int v = (t < NB) ? g_partial[t] : 0;
    sdata[t] = v;
    __syncthreads();
    for (int off = 1; off < 256; off <<= 1) {
        int x = (t >= off) ? sdata[t - off] : 0;
        __syncthreads();
        sdata[t] += x;
        __syncthreads();
    }
    if (t < NB) g_partial[t] = sdata[t] - v;
}

__global__ void k_scan3(int E) {
    int b = blockIdx.x, t = threadIdx.x;
    int add = g_partial[b];
    int base = b * SCAN_E + t * 4;
    #pragma unroll
    for (int i = 0; i < 4; i++) {
        int idx = base + i;
        if (idx < NR) {
            int val = g_offs[idx] + add;
            g_offs[idx] = val;
            g_cursor[idx] = val;
        }
    }
    if (b == 0 && t == 0) g_offs[NR] = E;
}

__global__ void k_fill_edges(const int* __restrict__ src,
                             const int* __restrict__ tgt,
                             const int* __restrict__ et, int E) {
    int e = blockIdx.x * blockDim.x + threadIdx.x;
    if (e < E) {
        int p = atomicAdd(&g_cursor[tgt[e] * RREL + et[e]], 1);
        g_csr[p] = src[e];
    }
}

// ---------------- weight packing: fp32 [k][64] -> bf16x2 pairs [k/2][64] ----------------
__global__ void k_pack_weights(const float* __restrict__ w1, const float* __restrict__ r1,
                               const float* __restrict__ w2, const float* __restrict__ r2,
                               const float* __restrict__ w3, const float* __restrict__ r3) {
    int i = blockIdx.x * blockDim.x + threadIdx.x;  // over 3 * 160 * 64
    if (i >= 3 * 160 * 64) return;
    int L = i / (160 * 64);
    int rem = i % (160 * 64);
    int k2 = rem >> 6, nn = rem & 63;
    const float* wp = (L == 0) ? w1 : (L == 1) ? w2 : w3;
    const float* rp = (L == 0) ? r1 : (L == 1) ? r2 : r3;
    float lo, hi;
    if (k2 < 128) { lo = wp[(2 * k2) * 64 + nn];        hi = wp[(2 * k2 + 1) * 64 + nn]; }
    else { int kk = k2 - 128; lo = rp[(2 * kk) * 64 + nn]; hi = rp[(2 * kk + 1) * 64 + nn]; }
    __nv_bfloat162 p = __floats2bfloat162_rn(lo, hi);
    g_Wpk[L][k2 * 64 + nn] = *(uint32_t*)&p;
}

// ---------------- node embedding -> bf16 packed ----------------
__global__ void k_embed(const int* __restrict__ x_op, const int* __restrict__ x_cat,
                        const float* __restrict__ op_emb, const float* __restrict__ cat_emb,
                        uint32_t* __restrict__ h, int n) {
    int i = blockIdx.x * blockDim.x + threadIdx.x;   // n*32 pairs
    if (i < n * 32) {
        int node = i >> 5, dp = i & 31;
        float2 a = *(const float2*)&op_emb[x_op[node] * DDIM + dp * 2];
        float2 b = *(const float2*)&cat_emb[x_cat[node] * DDIM + dp * 2];
        __nv_bfloat162 p = __floats2bfloat162_rn(a.x + b.x, a.y + b.y);
        h[i] = *(uint32_t*)&p;
    }
}

// ---------------- aggregation: warp/node, single merged loop over all 4 relations ----
// The node's 4 relation segments are contiguous in CSR: [b0,b4). One dual-edge
// pipelined loop with prefetched indices; relation selected arithmetically and
// accumulated into 4 named bf16x2 accumulator pairs.
__global__ void k_agg(const uint32_t* __restrict__ hin, int n) {
    int node = (blockIdx.x * blockDim.x + threadIdx.x) >> 5;
    int lane = threadIdx.x & 31;
    if (node >= n) return;
    int half = lane >> 4;       // which edge of the dual-gather this lane serves
    int sub  = lane & 15;       // 8-byte chunk within the 128-B h row

    int base = node * 4;
    int b0 = __ldg(&g_offs[base + 0]);
    int b1 = __ldg(&g_offs[base + 1]);
    int b2 = __ldg(&g_offs[base + 2]);
    int b3 = __ldg(&g_offs[base + 3]);
    int b4 = __ldg(&g_offs[base + 4]);

    __nv_bfloat162 z = __floats2bfloat162_rn(0.f, 0.f);
    __nv_bfloat162 aA0 = z, aA1 = z, aA2 = z, aA3 = z;
    __nv_bfloat162 aB0 = z, aB1 = z, aB2 = z, aB3 = z;

#define ACC_R(rr, vx, vy)                                                     \
    if ((rr) == 0)      { aA0 = __hadd2(aA0, vx); aB0 = __hadd2(aB0, vy); }   \
    else if ((rr) == 1) { aA1 = __hadd2(aA1, vx); aB1 = __hadd2(aB1, vy); }   \
    else if ((rr) == 2) { aA2 = __hadd2(aA2, vx); aB2 = __hadd2(aB2, vy); }   \
    else                { aA3 = __hadd2(aA3, vx); aB3 = __hadd2(aB3, vy); }

    int total = b4 - b0;
    int jend = b0 + (total & ~3);       // 4-edge main loop
    int i0 = 0, i1 = 0;
    if (b0 < jend) {
        i0 = __ldg(&g_csr[b0 + half]);
        i1 = __ldg(&g_csr[b0 + 2 + half]);
    }
    for (int j = b0; j < jend; j += 4) {
        uint2 u0 = __ldg((const uint2*)&hin[(size_t)i0 * 32 + sub * 2]);
        uint2 u1 = __ldg((const uint2*)&hin[(size_t)i1 * 32 + sub * 2]);
        int jn = j + 4;
        if (jn < jend) {                 // prefetch next pair of indices
            i0 = __ldg(&g_csr[jn + half]);
            i1 = __ldg(&g_csr[jn + 2 + half]);
        }
        int e0 = j + half, e1 = j + 2 + half;
        int r0 = (e0 >= b1) + (e0 >= b2) + (e0 >= b3);
        int r1 = (e1 >= b1) + (e1 >= b2) + (e1 >= b3);
        __nv_bfloat162 vx0 = *(__nv_bfloat162*)&u0.x, vy0 = *(__nv_bfloat162*)&u0.y;
        ACC_R(r0, vx0, vy0);
        __nv_bfloat162 vx1 = *(__nv_bfloat162*)&u1.x, vy1 = *(__nv_bfloat162*)&u1.y;
        ACC_R(r1, vx1, vy1);
    }
    // tail: 0..3 edges
    for (int j = jend; j < b4; j += 2) {
        int m = b4 - j;
        if (half == 0 || m >= 2) {
            int e = j + half;
            int idx = __ldg(&g_csr[e]);
            uint2 u = __ldg((const uint2*)&hin[(size_t)idx * 32 + sub * 2]);
            int r = (e >= b1) + (e >= b2) + (e >= b3);
            __nv_bfloat162 vx = *(__nv_bfloat162*)&u.x, vy = *(__nv_bfloat162*)&u.y;
            ACC_R(r, vx, vy);
        }
    }
#undef ACC_R

    // combine the two half-warps
#define CMB(a) { uint32_t ua = *(uint32_t*)&(a);                               \
                 uint32_t o = __shfl_down_sync(0xffffffffu, ua, 16);           \
                 (a) = __hadd2((a), *(__nv_bfloat162*)&o); }
    CMB(aA0) CMB(aB0) CMB(aA1) CMB(aB1) CMB(aA2) CMB(aB2) CMB(aA3) CMB(aB3)
#undef CMB

    if (half == 0) {
        size_t zbase = (size_t)node * 128 + sub * 2;
#define ST(rr, aa, bb, cnt) {                                                  \
        float inv = ((cnt) > 0) ? (1.f / (float)(cnt)) : 0.f;                  \
        float2 fa = __bfloat1622float2(aa), fb = __bfloat1622float2(bb);       \
        __nv_bfloat162 pa = __floats2bfloat162_rn(fa.x * inv, fa.y * inv);     \
        __nv_bfloat162 pb = __floats2bfloat162_rn(fb.x * inv, fb.y * inv);     \
        uint2 s; s.x = *(uint32_t*)&pa; s.y = *(uint32_t*)&pb;                 \
        *(uint2*)&g_Zp[zbase + (rr) * 32] = s; }
        ST(0, aA0, aB0, b1 - b0)
        ST(1, aA1, aB1, b2 - b1)
        ST(2, aA2, aB2, b3 - b2)
        ST(3, aA3, aB3, b4 - b3)
#undef ST
    }
}

// ---------------- bf16 tensor-core layer GEMM ----------------
__device__ __forceinline__ void mma_bf16(float* d,
                                         uint32_t a0, uint32_t a1, uint32_t a2, uint32_t a3,
                                         uint32_t b0, uint32_t b1) {
    asm volatile(
        "mma.sync.aligned.m16n8k16.row.col.f32.bf16.bf16.f32 "
        "{%0,%1,%2,%3}, {%4,%5,%6,%7}, {%8,%9}, {%0,%1,%2,%3};\n"
        : "+f"(d[0]), "+f"(d[1]), "+f"(d[2]), "+f"(d[3])
        : "r"(a0), "r"(a1), "r"(a2), "r"(a3), "r"(b0), "r"(b1));
}

#define AS_STRIDE 20   // uint32 units; conflict-free fragment loads
#define BS_STRIDE 72

__global__ __launch_bounds__(256) void k_gemm_tc(
        const uint32_t* __restrict__ hin,   // [n][32] packed
        const uint32_t* __restrict__ wpk,   // [160][64] packed (w ++ root)
        const float* __restrict__ bias,     // [64]
        uint32_t* __restrict__ hout,        // [n][32] packed
        int n, int doRelu) {
    __shared__ uint32_t As[128 * AS_STRIDE];
    __shared__ uint32_t Bs[16 * BS_STRIDE];

    int n0   = blockIdx.x * 128;
    int tid  = threadIdx.x;
    int warp = tid >> 5, lane = tid & 31;
    int gr = lane >> 2, ct = lane & 3;
    int warpM = warp * 16;

    float acc[8][4];
    #pragma unroll
    for (int i = 0; i < 8; i++)
        #pragma unroll
        for (int j = 0; j < 4; j++) acc[i][j] = 0.f;

    for (int kt = 0; kt < 10; kt++) {
        const uint32_t* Aptr; int lda, kb2;
        if (kt < 8) { Aptr = g_Zp; lda = 128; kb2 = kt * 16; }
        else        { Aptr = hin;  lda = 32;  kb2 = (kt - 8) * 16; }
        const uint32_t* Bptr = wpk + kt * 16 * 64;

        #pragma unroll
        for (int it = 0; it < 2; it++) {
            int i = tid + it * 256;
            int r = i >> 2, c4 = i & 3;
            int row = n0 + r;
            uint4 v = make_uint4(0u, 0u, 0u, 0u);
            if (row < n) v = *(const uint4*)&Aptr[(size_t)row * lda + kb2 + c4 * 4];
            *(uint4*)&As[r * AS_STRIDE + c4 * 4] = v;
        }
        {
            int r = tid >> 4, c4 = tid & 15;
            uint4 v = *(const uint4*)&Bptr[r * 64 + c4 * 4];
            *(uint4*)&Bs[r * BS_STRIDE + c4 * 4] = v;
        }
        __syncthreads();

        #pragma unroll
        for (int k16 = 0; k16 < 2; k16++) {
            int k2b = k16 * 8;
            uint32_t a0 = As[(warpM + gr)     * AS_STRIDE + k2b + ct];
            uint32_t a1 = As[(warpM + gr + 8) * AS_STRIDE + k2b + ct];
            uint32_t a2 = As[(warpM + gr)     * AS_STRIDE + k2b + ct + 4];
            uint32_t a3 = As[(warpM + gr + 8) * AS_STRIDE + k2b + ct + 4];
            #pragma unroll
            for (int nt = 0; nt < 8; nt++) {
                uint32_t b0 = Bs[(k2b + ct)     * BS_STRIDE + nt * 8 + gr];
                uint32_t b1 = Bs[(k2b + ct + 4) * BS_STRIDE + nt * 8 + gr];
                mma_bf16(acc[nt], a0, a1, a2, a3, b0, b1);
            }
        }
        __syncthreads();
    }

    int r0 = n0 + warpM + gr;
    int r1 = r0 + 8;
    #pragma unroll
    for (int nt = 0; nt < 8; nt++) {
        int col = nt * 8 + 2 * ct;
        float bb0 = bias[col], bb1 = bias[col + 1];
        float v00 = acc[nt][0] + bb0, v01 = acc[nt][1] + bb1;
        float v10 = acc[nt][2] + bb0, v11 = acc[nt][3] + bb1;
        if (doRelu) {
            v00 = fmaxf(v00, 0.f); v01 = fmaxf(v01, 0.f);
            v10 = fmaxf(v10, 0.f); v11 = fmaxf(v11, 0.f);
        }
        if (r0 < n) {
            __nv_bfloat162 p = __floats2bfloat162_rn(v00, v01);
            hout[(size_t)r0 * 32 + (col >> 1)] = *(uint32_t*)&p;
        }
        if (r1 < n) {
            __nv_bfloat162 p = __floats2bfloat162_rn(v10, v11);
            hout[(size_t)r1 * 32 + (col >> 1)] = *(uint32_t*)&p;
        }
    }
}

// ---------------- pooling (batch is sorted) ----------------
__device__ __forceinline__ int dev_lower_bound(const int* a, int n, int key) {
    int lo = 0, hi = n;
    while (lo < hi) { int mid = (lo + hi) >> 1; if (a[mid] < key) lo = mid + 1; else hi = mid; }
    return lo;
}

__global__ void k_pool(const uint32_t* __restrict__ h, const int* __restrict__ batch, int n) {
    int g = blockIdx.x;
    int lo = dev_lower_bound(batch, n, g);
    int hi = dev_lower_bound(batch, n, g + 1);
    __shared__ float sacc[8][64];
    int dp = threadIdx.x & 31, part = threadIdx.x >> 5;
    float s0 = 0.f, s1 = 0.f;
    for (int i = lo + part; i < hi; i += 8) {
        uint32_t u = h[(size_t)i * 32 + dp];
        float2 f = __bfloat1622float2(*(__nv_bfloat162*)&u);
        s0 += f.x; s1 += f.y;
    }
    sacc[part][dp * 2] = s0;
    sacc[part][dp * 2 + 1] = s1;
    __syncthreads();
    if (part < 2) {
        int d = part * 32 + dp;
        float tot = 0.f;
        #pragma unroll
        for (int p = 0; p < 8; p++) tot += sacc[p][d];
        float c = (float)(hi - lo);
        g_pooled[g * DDIM + d] = tot / fmaxf(c, 1.f);
    }
}

// ---------------- MLP head + log_softmax ----------------
__global__ void k_head(const float* __restrict__ fc1w, const float* __restrict__ fc1b,
                       const float* __restrict__ fc2w, const float* __restrict__ fc2b,
                       float* __restrict__ out) {
    __shared__ float w1s[64 * 64];
    for (int i = threadIdx.x; i < 64 * 64; i += 64) w1s[i] = fc1w[i];
    __syncthreads();
    int g = threadIdx.x;
    float p[64];
    #pragma unroll
    for (int d = 0; d < 64; d++) p[d] = g_pooled[g * 64 + d];
    float hid[64];
    #pragma unroll 4
    for (int e = 0; e < 64; e++) {
        float s = fc1b[e];
        #pragma unroll
        for (int d = 0; d < 64; d++) s += p[d] * w1s[d * 64 + e];
        hid[e] = fmaxf(s, 0.f);
    }
    float lg[CC];
    #pragma unroll
    for (int c = 0; c < CC; c++) {
        float s = fc2b[c];
        #pragma unroll 4
        for (int e = 0; e < 64; e++) s += hid[e] * fc2w[e * CC + c];
        lg[c] = s;
    }
    float m = lg[0];
    #pragma unroll
    for (int c = 1; c < CC; c++) m = fmaxf(m, lg[c]);
    float sum = 0.f;
    #pragma unroll
    for (int c = 0; c < CC; c++) sum += expf(lg[c] - m);
    float lse = logf(sum);
    #pragma unroll
    for (int c = 0; c < CC; c++) out[g * CC + c] = lg[c] - m - lse;
}

// ---------------- launch ----------------
extern "C" void kernel_launch(void* const* d_in, const int* in_sizes, int n_in,
                              void* d_out, int out_size) {
    const int*   x_op    = (const int*)  d_in[0];
    const int*   x_cat   = (const int*)  d_in[1];
    const int*   eidx    = (const int*)  d_in[2];
    const int*   etype   = (const int*)  d_in[3];
    const int*   batch   = (const int*)  d_in[4];
    const float* op_emb  = (const float*)d_in[5];
    const float* cat_emb = (const float*)d_in[6];
    const float* w1 = (const float*)d_in[7],  *r1 = (const float*)d_in[8],  *b1 = (const float*)d_in[9];
    const float* w2 = (const float*)d_in[10], *r2 = (const float*)d_in[11], *b2 = (const float*)d_in[12];
    const float* w3 = (const float*)d_in[13], *r3 = (const float*)d_in[14], *b3 = (const float*)d_in[15];
    const float* fc1w = (const float*)d_in[16], *fc1b = (const float*)d_in[17];
    const float* fc2w = (const float*)d_in[18], *fc2b = (const float*)d_in[19];
    float* out = (float*)d_out;

    int n = in_sizes[0];
    int E = in_sizes[3];
    const int* src = eidx;
    const int* tgt = eidx + E;

    uint32_t* hA;  cudaGetSymbolAddress((void**)&hA, g_hA);
    uint32_t* hB;  cudaGetSymbolAddress((void**)&hB, g_hB);
    uint32_t* Wpk; cudaGetSymbolAddress((void**)&Wpk, g_Wpk);

    int NB = (NR + SCAN_E - 1) / SCAN_E;  // 196

    // CSR build (reused across all 3 layers)
    k_zero_cnt<<<(NR + 255) / 256, 256>>>();
    k_count_edges<<<(E + 255) / 256, 256>>>(tgt, etype, E);
    k_scan1<<<NB, SCAN_T>>>();
    k_scan2<<<1, 256>>>(NB);
    k_scan3<<<NB, SCAN_T>>>(E);
    k_fill_edges<<<(E + 255) / 256, 256>>>(src, tgt, etype, E);

    // pack weights + embedding
    k_pack_weights<<<(3 * 160 * 64 + 255) / 256, 256>>>(w1, r1, w2, r2, w3, r3);
    k_embed<<<(n * 32 + 255) / 256, 256>>>(x_op, x_cat, op_emb, cat_emb, hA, n);

    int aggBlocks  = (n + 7) / 8;          // 8 warps (nodes) per 256-thread block
    int gemmBlocks = (n + 127) / 128;

    // layer 1: hA -> hB (relu)
    k_agg<<<aggBlocks, 256>>>(hA, n);
    k_gemm_tc<<<gemmBlocks, 256>>>(hA, Wpk + 0 * 160 * 64, b1, hB, n, 1);
    // layer 2: hB -> hA (relu)
    k_agg<<<aggBlocks, 256>>>(hB, n);
    k_gemm_tc<<<gemmBlocks, 256>>>(hB, Wpk + 1 * 160 * 64, b2, hA, n, 1);
    // layer 3: hA -> hB (no relu)
    k_agg<<<aggBlocks, 256>>>(hA, n);
    k_gemm_tc<<<gemmBlocks, 256>>>(hA, Wpk + 2 * 160 * 64, b3, hB, n, 0);

    // pool + head
    k_pool<<<GG, 256>>>(hB, batch, n);
    k_head<<<1, 64>>>(fc1w, fc1b, fc2w, fc2b, out);
}

// round 9
// speedup vs baseline: 1.1056x; 1.1056x over previous
#include <cuda_runtime.h>
#include <cuda_bf16.h>
#include <math.h>
#include <stdint.h>

// Problem constants (fixed by the dataset)
#define NMAX 200000
#define EMAX 4000000
#define RREL 4
#define DDIM 64
#define NR   (NMAX * RREL)     // 800000
#define GG   64
#define CC   10

// ---------------- scratch (static __device__, no allocation) ----------------
__device__ int      g_cnt[NR];
__device__ int      g_offs[NR + 1];
__device__ int      g_cursor[NR];
__device__ int      g_csr[EMAX];
__device__ int      g_partial[256];
__device__ uint32_t g_hA[(size_t)NMAX * 32];          // bf16x2 packed, 64 dims/node
__device__ uint32_t g_hB[(size_t)NMAX * 32];
__device__ uint32_t g_Zp[(size_t)NMAX * 128];         // bf16x2 packed, 256 cols/node
__device__ uint32_t g_Wpk[3][160 * 64];               // packed bf16x2 weights: [k2][n]
__device__ float    g_pooled[GG * DDIM];

// ---------------- launch 0: zero counters + pack weights (fused) ----------------
__global__ void k_init_pack(const float* __restrict__ w1, const float* __restrict__ r1,
                            const float* __restrict__ w2, const float* __restrict__ r2,
                            const float* __restrict__ w3, const float* __restrict__ r3) {
    int i = blockIdx.x * blockDim.x + threadIdx.x;
    if (i < NR) g_cnt[i] = 0;
    if (i < 3 * 160 * 64) {
        int L = i / (160 * 64);
        int rem = i % (160 * 64);
        int k2 = rem >> 6, nn = rem & 63;
        const float* wp = (L == 0) ? w1 : (L == 1) ? w2 : w3;
        const float* rp = (L == 0) ? r1 : (L == 1) ? r2 : r3;
        float lo, hi;
        if (k2 < 128) { lo = wp[(2 * k2) * 64 + nn];        hi = wp[(2 * k2 + 1) * 64 + nn]; }
        else { int kk = k2 - 128; lo = rp[(2 * kk) * 64 + nn]; hi = rp[(2 * kk + 1) * 64 + nn]; }
        __nv_bfloat162 p = __floats2bfloat162_rn(lo, hi);
        g_Wpk[L][k2 * 64 + nn] = *(uint32_t*)&p;
    }
}

// ---------------- launch 1: count edges + node embedding (fused) ----------------
__global__ void k_count_embed(const int* __restrict__ tgt, const int* __restrict__ et, int E,
                              const int* __restrict__ x_op, const int* __restrict__ x_cat,
                              const float* __restrict__ op_emb, const float* __restrict__ cat_emb,
                              uint32_t* __restrict__ h, int n) {
    int i = blockIdx.x * blockDim.x + threadIdx.x;
    if (i < E) atomicAdd(&g_cnt[tgt[i] * RREL + et[i]], 1);
    if (i < n * 32) {
        int node = i >> 5, dp = i & 31;
        float2 a = *(const float2*)&op_emb[x_op[node] * DDIM + dp * 2];
        float2 b = *(const float2*)&cat_emb[x_cat[node] * DDIM + dp * 2];
        __nv_bfloat162 p = __floats2bfloat162_rn(a.x + b.x, a.y + b.y);
        h[i] = *(uint32_t*)&p;
    }
}

// ---------------- launch 2: per-block scan of g_cnt -> g_offs + block totals ----
#define SCAN_T 1024
#define SCAN_E 4096     // 4 per thread
__global__ void k_scan1() {
    __shared__ int sdata[SCAN_T];
    int b = blockIdx.x, t = threadIdx.x;
    int base = b * SCAN_E + t * 4;
    int v0 = (base + 0 < NR) ? g_cnt[base + 0] : 0;
    int v1 = (base + 1 < NR) ? g_cnt[base + 1] : 0;
    int v2 = (base + 2 < NR) ? g_cnt[base + 2] : 0;
    int v3 = (base + 3 < NR) ? g_cnt[base + 3] : 0;
    int tot = v0 + v1 + v2 + v3;
    sdata[t] = tot;
    __syncthreads();
    for (int off = 1; off < SCAN_T; off <<= 1) {
        int x = (t >= off) ? sdata[t - off] : 0;
        __syncthreads();
        sdata[t] += x;
        __syncthreads();
    }
    int excl = sdata[t] - tot;
    if (base + 0 < NR) g_offs[base + 0] = excl;
    if (base + 1 < NR) g_offs[base + 1] = excl + v0;
    if (base + 2 < NR) g_offs[base + 2] = excl + v0 + v1;
    if (base + 3 < NR) g_offs[base + 3] = excl + v0 + v1 + v2;
    if (t == SCAN_T - 1) g_partial[b] = sdata[SCAN_T - 1];
}

// ---------------- launch 3: scan3 with local re-scan of block partials (scan2 fused) ----
__global__ void k_scan3(int E, int NB) {
    __shared__ int sp[256];
    int b = blockIdx.x, t = threadIdx.x;
    if (t < 256) sp[t] = (t < NB) ? g_partial[t] : 0;
    __syncthreads();
    // inclusive Hillis-Steele scan of the 256-entry partial array
    for (int off = 1; off < 256; off <<= 1) {
        int x = (t >= off && t < 256) ? sp[t - off] : 0;
        __syncthreads();
        if (t < 256) sp[t] += x;
        __syncthreads();
    }
    int add = (b == 0) ? 0 : sp[b - 1];   // exclusive prefix for this block
    int base = b * SCAN_E + t * 4;
    #pragma unroll
    for (int i = 0; i < 4; i++) {
        int idx = base + i;
        if (idx < NR) {
            int val = g_offs[idx] + add;
            g_offs[idx] = val;
            g_cursor[idx] = val;
        }
    }
    if (b == 0 && t == 0) g_offs[NR] = E;
}

// ---------------- launch 4: fill CSR ----------------
__global__ void k_fill_edges(const int* __restrict__ src,
                             const int* __restrict__ tgt,
                             const int* __restrict__ et, int E) {
    int e = blockIdx.x * blockDim.x + threadIdx.x;
    if (e < E) {
        int p = atomicAdd(&g_cursor[tgt[e] * RREL + et[e]], 1);
        g_csr[p] = src[e];
    }
}

// ---------------- aggregation: warp per node, dual-edge gathers + HADD2 ----------------
// (byte-identical to the 754us R7 build)
__global__ void k_agg(const uint32_t* __restrict__ hin, int n) {
    int node = (blockIdx.x * blockDim.x + threadIdx.x) >> 5;
    int lane = threadIdx.x & 31;
    if (node >= n) return;
    int half = lane >> 4;       // which edge of the pair this lane serves
    int sub  = lane & 15;       // 8-byte chunk within the h row
    size_t zbase = (size_t)node * 128;

    int base = node * 4;
    int b0 = __ldg(&g_offs[base + 0]);
    int b1 = __ldg(&g_offs[base + 1]);
    int b2 = __ldg(&g_offs[base + 2]);
    int b3 = __ldg(&g_offs[base + 3]);
    int b4 = __ldg(&g_offs[base + 4]);

    #pragma unroll
    for (int r = 0; r < 4; r++) {
        int s = (r == 0) ? b0 : (r == 1) ? b1 : (r == 2) ? b2 : b3;
        int e = (r == 0) ? b1 : (r == 1) ? b2 : (r == 2) ? b3 : b4;
        int cnt = e - s;
        __nv_bfloat162 accA = __floats2bfloat162_rn(0.f, 0.f);
        __nv_bfloat162 accB = accA;
        int j = s;
        // 4 edges per iteration: 2 dual-gathers
        for (; j + 3 < e; j += 4) {
            int i0 = __ldg(&g_csr[j + half]);
            int i1 = __ldg(&g_csr[j + 2 + half]);
            uint2 u0 = __ldg((const uint2*)&hin[(size_t)i0 * 32 + sub * 2]);
            uint2 u1 = __ldg((const uint2*)&hin[(size_t)i1 * 32 + sub * 2]);
            accA = __hadd2(accA, __hadd2(*(__nv_bfloat162*)&u0.x, *(__nv_bfloat162*)&u1.x));
            accB = __hadd2(accB, __hadd2(*(__nv_bfloat162*)&u0.y, *(__nv_bfloat162*)&u1.y));
        }
        if (e - j >= 2) {
            int i0 = __ldg(&g_csr[j + half]);
            uint2 u0 = __ldg((const uint2*)&hin[(size_t)i0 * 32 + sub * 2]);
            accA = __hadd2(accA, *(__nv_bfloat162*)&u0.x);
            accB = __hadd2(accB, *(__nv_bfloat162*)&u0.y);
            j += 2;
        }
        if (j < e) {
            int i0 = __ldg(&g_csr[j]);
            if (half == 0) {
                uint2 u0 = __ldg((const uint2*)&hin[(size_t)i0 * 32 + sub * 2]);
                accA = __hadd2(accA, *(__nv_bfloat162*)&u0.x);
                accB = __hadd2(accB, *(__nv_bfloat162*)&u0.y);
            }
        }
        // combine the two half-warps
        uint32_t ua = *(uint32_t*)&accA, ub = *(uint32_t*)&accB;
        uint32_t oa = __shfl_down_sync(0xffffffffu, ua, 16);
        uint32_t ob = __shfl_down_sync(0xffffffffu, ub, 16);
        accA = __hadd2(accA, *(__nv_bfloat162*)&oa);
        accB = __hadd2(accB, *(__nv_bfloat162*)&ob);
        if (half == 0) {
            float2 fA = __bfloat1622float2(accA);
            float2 fB = __bfloat1622float2(accB);
            float inv = (cnt > 0) ? (1.f / (float)cnt) : 0.f;
            __nv_bfloat162 pA = __floats2bfloat162_rn(fA.x * inv, fA.y * inv);
            __nv_bfloat162 pB = __floats2bfloat162_rn(fB.x * inv, fB.y * inv);
            uint2 stv; stv.x = *(uint32_t*)&pA; stv.y = *(uint32_t*)&pB;
            *(uint2*)&g_Zp[zbase + r * 32 + sub * 2] = stv;
        }
    }
}

// ---------------- bf16 tensor-core layer GEMM ----------------
__device__ __forceinline__ void mma_bf16(float* d,
                                         uint32_t a0, uint32_t a1, uint32_t a2, uint32_t a3,
                                         uint32_t b0, uint32_t b1) {
    asm volatile(
        "mma.sync.aligned.m16n8k16.row.col.f32.bf16.bf16.f32 "
        "{%0,%1,%2,%3}, {%4,%5,%6,%7}, {%8,%9}, {%0,%1,%2,%3};\n"
        : "+f"(d[0]), "+f"(d[1]), "+f"(d[2]), "+f"(d[3])
        : "r"(a0), "r"(a1), "r"(a2), "r"(a3), "r"(b0), "r"(b1));
}

#define AS_STRIDE 20   // uint32 units; conflict-free fragment loads
#define BS_STRIDE 72

__global__ __launch_bounds__(256) void k_gemm_tc(
        const uint32_t* __restrict__ hin,   // [n][32] packed
        const uint32_t* __restrict__ wpk,   // [160][64] packed (w ++ root)
        const float* __restrict__ bias,     // [64]
        uint32_t* __restrict__ hout,        // [n][32] packed
        int n, int doRelu) {
    __shared__ uint32_t As[128 * AS_STRIDE];
    __shared__ uint32_t Bs[16 * BS_STRIDE];

    int n0   = blockIdx.x * 128;
    int tid  = threadIdx.x;
    int warp = tid >> 5, lane = tid & 31;
    int gr = lane >> 2, ct = lane & 3;
    int warpM = warp * 16;

    float acc[8][4];
    #pragma unroll
    for (int i = 0; i < 8; i++)
        #pragma unroll
        for (int j = 0; j < 4; j++) acc[i][j] = 0.f;

    for (int kt = 0; kt < 10; kt++) {
        const uint32_t* Aptr; int lda, kb2;
        if (kt < 8) { Aptr = g_Zp; lda = 128; kb2 = kt * 16; }
        else        { Aptr = hin;  lda = 32;  kb2 = (kt - 8) * 16; }
        const uint32_t* Bptr = wpk + kt * 16 * 64;

        #pragma unroll
        for (int it = 0; it < 2; it++) {
            int i = tid + it * 256;
            int r = i >> 2, c4 = i & 3;
            int row = n0 + r;
            uint4 v = make_uint4(0u, 0u, 0u, 0u);
            if (row < n) v = *(const uint4*)&Aptr[(size_t)row * lda + kb2 + c4 * 4];
            *(uint4*)&As[r * AS_STRIDE + c4 * 4] = v;
        }
        {
            int r = tid >> 4, c4 = tid & 15;
            uint4 v = *(const uint4*)&Bptr[r * 64 + c4 * 4];
            *(uint4*)&Bs[r * BS_STRIDE + c4 * 4] = v;
        }
        __syncthreads();

        #pragma unroll
        for (int k16 = 0; k16 < 2; k16++) {
            int k2b = k16 * 8;
            uint32_t a0 = As[(warpM + gr)     * AS_STRIDE + k2b + ct];
            uint32_t a1 = As[(warpM + gr + 8) * AS_STRIDE + k2b + ct];
            uint32_t a2 = As[(warpM + gr)     * AS_STRIDE + k2b + ct + 4];
            uint32_t a3 = As[(warpM + gr + 8) * AS_STRIDE + k2b + ct + 4];
            #pragma unroll
            for (int nt = 0; nt < 8; nt++) {
                uint32_t b0 = Bs[(k2b + ct)     * BS_STRIDE + nt * 8 + gr];
                uint32_t b1 = Bs[(k2b + ct + 4) * BS_STRIDE + nt * 8 + gr];
                mma_bf16(acc[nt], a0, a1, a2, a3, b0, b1);
            }
        }
        __syncthreads();
    }

    int r0 = n0 + warpM + gr;
    int r1 = r0 + 8;
    #pragma unroll
    for (int nt = 0; nt < 8; nt++) {
        int col = nt * 8 + 2 * ct;
        float bb0 = bias[col], bb1 = bias[col + 1];
        float v00 = acc[nt][0] + bb0, v01 = acc[nt][1] + bb1;
        float v10 = acc[nt][2] + bb0, v11 = acc[nt][3] + bb1;
        if (doRelu) {
            v00 = fmaxf(v00, 0.f); v01 = fmaxf(v01, 0.f);
            v10 = fmaxf(v10, 0.f); v11 = fmaxf(v11, 0.f);
        }
        if (r0 < n) {
            __nv_bfloat162 p = __floats2bfloat162_rn(v00, v01);
            hout[(size_t)r0 * 32 + (col >> 1)] = *(uint32_t*)&p;
        }
        if (r1 < n) {
            __nv_bfloat162 p = __floats2bfloat162_rn(v10, v11);
            hout[(size_t)r1 * 32 + (col >> 1)] = *(uint32_t*)&p;
        }
    }
}

// ---------------- pooling (batch is sorted) ----------------
__device__ __forceinline__ int dev_lower_bound(const int* a, int n, int key) {
    int lo = 0, hi = n;
    while (lo < hi) { int mid = (lo + hi) >> 1; if (a[mid] < key) lo = mid + 1; else hi = mid; }
    return lo;
}

__global__ void k_pool(const uint32_t* __restrict__ h, const int* __restrict__ batch, int n) {
    int g = blockIdx.x;
    int lo = dev_lower_bound(batch, n, g);
    int hi = dev_lower_bound(batch, n, g + 1);
    __shared__ float sacc[8][64];
    int dp = threadIdx.x & 31, part = threadIdx.x >> 5;
    float s0 = 0.f, s1 = 0.f;
    for (int i = lo + part; i < hi; i += 8) {
        uint32_t u = h[(size_t)i * 32 + dp];
        float2 f = __bfloat1622float2(*(__nv_bfloat162*)&u);
        s0 += f.x; s1 += f.y;
    }
    sacc[part][dp * 2] = s0;
    sacc[part][dp * 2 + 1] = s1;
    __syncthreads();
    if (part < 2) {
        int d = part * 32 + dp;
        float tot = 0.f;
        #pragma unroll
        for (int p = 0; p < 8; p++) tot += sacc[p][d];
        float c = (float)(hi - lo);
        g_pooled[g * DDIM + d] = tot / fmaxf(c, 1.f);
    }
}

// ---------------- MLP head + log_softmax ----------------
__global__ void k_head(const float* __restrict__ fc1w, const float* __restrict__ fc1b,
                       const float* __restrict__ fc2w, const float* __restrict__ fc2b,
                       float* __restrict__ out) {
    __shared__ float w1s[64 * 64];
    for (int i = threadIdx.x; i < 64 * 64; i += 64) w1s[i] = fc1w[i];
    __syncthreads();
    int g = threadIdx.x;
    float p[64];
    #pragma unroll
    for (int d = 0; d < 64; d++) p[d] = g_pooled[g * 64 + d];
    float hid[64];
    #pragma unroll 4
    for (int e = 0; e < 64; e++) {
        float s = fc1b[e];
        #pragma unroll
        for (int d = 0; d < 64; d++) s += p[d] * w1s[d * 64 + e];
        hid[e] = fmaxf(s, 0.f);
    }
    float lg[CC];
    #pragma unroll
    for (int c = 0; c < CC; c++) {
        float s = fc2b[c];
        #pragma unroll 4
        for (int e = 0; e < 64; e++) s += hid[e] * fc2w[e * CC + c];
        lg[c] = s;
    }
    float m = lg[0];
    #pragma unroll
    for (int c = 1; c < CC; c++) m = fmaxf(m, lg[c]);
    float sum = 0.f;
    #pragma unroll
    for (int c = 0; c < CC; c++) sum += expf(lg[c] - m);
    float lse = logf(sum);
    #pragma unroll
    for (int c = 0; c < CC; c++) out[g * CC + c] = lg[c] - m - lse;
}

// ---------------- launch ----------------
extern "C" void kernel_launch(void* const* d_in, const int* in_sizes, int n_in,
                              void* d_out, int out_size) {
    const int*   x_op    = (const int*)  d_in[0];
    const int*   x_cat   = (const int*)  d_in[1];
    const int*   eidx    = (const int*)  d_in[2];
    const int*   etype   = (const int*)  d_in[3];
    const int*   batch   = (const int*)  d_in[4];
    const float* op_emb  = (const float*)d_in[5];
    const float* cat_emb = (const float*)d_in[6];
    const float* w1 = (const float*)d_in[7],  *r1 = (const float*)d_in[8],  *b1 = (const float*)d_in[9];
    const float* w2 = (const float*)d_in[10], *r2 = (const float*)d_in[11], *b2 = (const float*)d_in[12];
    const float* w3 = (const float*)d_in[13], *r3 = (const float*)d_in[14], *b3 = (const float*)d_in[15];
    const float* fc1w = (const float*)d_in[16], *fc1b = (const float*)d_in[17];
    const float* fc2w = (const float*)d_in[18], *fc2b = (const float*)d_in[19];
    float* out = (float*)d_out;

    int n = in_sizes[0];
    int E = in_sizes[3];
    const int* src = eidx;
    const int* tgt = eidx + E;

    uint32_t* hA;  cudaGetSymbolAddress((void**)&hA, g_hA);
    uint32_t* hB;  cudaGetSymbolAddress((void**)&hB, g_hB);
    uint32_t* Wpk; cudaGetSymbolAddress((void**)&Wpk, g_Wpk);

    int NB = (NR + SCAN_E - 1) / SCAN_E;  // 196

    // launch 0: zero counters + pack weights
    k_init_pack<<<(NR + 255) / 256, 256>>>(w1, r1, w2, r2, w3, r3);
    // launch 1: count edges + embed nodes
    {
        int tot = (E > n * 32) ? E : n * 32;
        k_count_embed<<<(tot + 255) / 256, 256>>>(tgt, etype, E,
                                                  x_op, x_cat, op_emb, cat_emb, hA, n);
    }
    // launch 2-3: scan
    k_scan1<<<NB, SCAN_T>>>();
    k_scan3<<<NB, SCAN_T>>>(E, NB);
    // launch 4: fill CSR
    k_fill_edges<<<(E + 255) / 256, 256>>>(src, tgt, etype, E);

    int aggBlocks  = (n + 7) / 8;          // 8 warps (nodes) per 256-thread block
    int gemmBlocks = (n + 127) / 128;

    // launch 5: first agg  <-- ncu -s 5 -c 1 captures THIS
    k_agg<<<aggBlocks, 256>>>(hA, n);
    k_gemm_tc<<<gemmBlocks, 256>>>(hA, Wpk + 0 * 160 * 64, b1, hB, n, 1);
    // layer 2: hB -> hA (relu)
    k_agg<<<aggBlocks, 256>>>(hB, n);
    k_gemm_tc<<<gemmBlocks, 256>>>(hB, Wpk + 1 * 160 * 64, b2, hA, n, 1);
    // layer 3: hA -> hB (no relu)
    k_agg<<<aggBlocks, 256>>>(hA, n);
    k_gemm_tc<<<gemmBlocks, 256>>>(hA, Wpk + 2 * 160 * 64, b3, hB, n, 0);

    // pool + head
    k_pool<<<GG, 256>>>(hB, batch, n);
    k_head<<<1, 64>>>(fc1w, fc1b, fc2w, fc2b, out);
}